// round 17
// baseline (speedup 1.0000x reference)
#include <cuda_runtime.h>
#include <cuda_bf16.h>
#include <cstdint>

#define B 8
#define L 4096
#define F 64
#define TM 128           // i-rows per CTA
#define KC 32            // j (K) chunk per stage
#define NC (L / KC)      // 128 chunks
#define NSTAGE 4
#define AW 36            // smem row stride in words (32 + 4 pad) -> conflict-free
#define ROWB (AW * 4)    // 144 bytes per row

// Scratch: hiddenT as tf32-rounded fp32, layout [b][o][j] (o-major, j contiguous)
__device__ float g_hT[(size_t)B * F * L];

// ---------------- smem map (bytes) ----------------
// per stage: A = 128*144 = 18432, B = 64*144 = 9216 -> 27648
#define STAGE_BYTES 27648
#define A_OFF(s) ((s) * STAGE_BYTES)
#define B_OFF(s) ((s) * STAGE_BYTES + 18432)
#define BIAS_OFF (NSTAGE * STAGE_BYTES)
#define SMEM_BYTES (BIAS_OFF + 256)

__device__ __forceinline__ uint32_t smem_u32(const void* p) {
    uint32_t a;
    asm("{ .reg .u64 t; cvta.to.shared.u64 t, %1; cvt.u32.u64 %0, t; }" : "=r"(a) : "l"(p));
    return a;
}
__device__ __forceinline__ void cp16(uint32_t dst, const void* src) {
    asm volatile("cp.async.cg.shared.global [%0], [%1], 16;" :: "r"(dst), "l"(src));
}
__device__ __forceinline__ void cp_commit() { asm volatile("cp.async.commit_group;"); }
template <int N> __device__ __forceinline__ void cp_wait() {
    asm volatile("cp.async.wait_group %0;" :: "n"(N));
}
__device__ __forceinline__ void ldsm4(uint32_t* r, uint32_t addr) {
    asm volatile("ldmatrix.sync.aligned.m8n8.x4.shared.b16 {%0,%1,%2,%3}, [%4];"
                 : "=r"(r[0]), "=r"(r[1]), "=r"(r[2]), "=r"(r[3]) : "r"(addr));
}
__device__ __forceinline__ uint32_t f2tf32(float v) {
    uint32_t u;
    asm("cvt.rna.tf32.f32 %0, %1;" : "=r"(u) : "f"(v));
    return u;
}
__device__ __forceinline__ void mma_tf32(float* c, const uint32_t* a, uint32_t b0, uint32_t b1) {
    asm volatile(
        "mma.sync.aligned.m16n8k8.row.col.f32.tf32.tf32.f32 "
        "{%0,%1,%2,%3}, {%4,%5,%6,%7}, {%8,%9}, {%0,%1,%2,%3};"
        : "+f"(c[0]), "+f"(c[1]), "+f"(c[2]), "+f"(c[3])
        : "r"(a[0]), "r"(a[1]), "r"(a[2]), "r"(a[3]), "r"(b0), "r"(b1));
}

// ---------------------------------------------------------------------------
// Kernel 1: hiddenT[b][o][j] = tf32_round( sum_f text[b][j][f] * W[f][o] )
// 512 threads: 8 row-groups x 64 o-lanes, 8 rows per thread.
// ---------------------------------------------------------------------------
__global__ __launch_bounds__(512) void hiddenT_kernel(
    const float* __restrict__ text, const float* __restrict__ W)
{
    __shared__ float w_s[F][F];
    __shared__ float tb[64][65];

    const int tid  = threadIdx.x;
    const int b    = blockIdx.y;
    const int row0 = blockIdx.x * 64;

    for (int idx = tid; idx < F * F; idx += 512)
        w_s[idx >> 6][idx & 63] = W[idx];

    const float* tptr = text + ((size_t)b * L + row0) * F;
    for (int idx = tid; idx < 64 * F; idx += 512)
        tb[idx >> 6][idx & 63] = tptr[idx];
    __syncthreads();

    const int o  = tid & 63;
    const int ig = tid >> 6;   // 0..7, 8 rows each

    float acc[8];
#pragma unroll
    for (int r = 0; r < 8; ++r) {
        const int j = ig * 8 + r;
        float a = 0.f;
#pragma unroll
        for (int f = 0; f < F; ++f)
            a = fmaf(tb[j][f], w_s[f][o], a);
        acc[r] = a;
    }
    __syncthreads();

#pragma unroll
    for (int r = 0; r < 8; ++r)
        tb[o][ig * 8 + r] = acc[r];
    __syncthreads();

    for (int idx = tid; idx < 64 * 64; idx += 512) {
        const int o2 = idx >> 6;
        const int jj = idx & 63;
        uint32_t t = f2tf32(tb[o2][jj]);
        g_hT[((size_t)b * F + o2) * L + row0 + jj] = __uint_as_float(t);
    }
}

// ---------------------------------------------------------------------------
// Kernel 2: TF32 warp-MMA GEMM. 256 threads = 8 warps, 4m x 2n layout,
// warp tile 32x32 over the CTA tile 128x64. 4-stage cp.async, wait_group<2>.
// out[b][i][o] = sum_j adj[b][i][j] * hiddenT[b][o][j] + bias[o]
// ---------------------------------------------------------------------------
__global__ __launch_bounds__(256, 2) void gemm_mma_kernel(
    const float* __restrict__ adj, const float* __restrict__ bias,
    float* __restrict__ out)
{
    extern __shared__ __align__(1024) char sm[];
    const uint32_t smb = smem_u32(sm);
    const int tid  = threadIdx.x;
    const int w    = tid >> 5;
    const int wm   = w & 3;       // m group: rows wm*32..+31
    const int wn   = w >> 2;      // n group: cols wn*32..+31
    const int lane = tid & 31;
    const int gr   = lane >> 2;   // 0..7
    const int cq   = lane & 3;    // 0..3
    const int b    = blockIdx.y;
    const int i0   = blockIdx.x * TM;

    const float* adjBase = adj + ((size_t)b * L + i0) * L;
    const float* hT      = g_hT + (size_t)b * F * L;

    if (tid < 64) ((float*)(sm + BIAS_OFF))[tid] = bias[tid];

    float c[2][4][4];
#pragma unroll
    for (int mg = 0; mg < 2; ++mg)
#pragma unroll
        for (int n = 0; n < 4; ++n)
#pragma unroll
            for (int r = 0; r < 4; ++r) c[mg][n][r] = 0.f;

    // per-chunk prefetch: A 1024 cp16 (4/thread), B 512 cp16 (2/thread)
    auto prefetch = [&](int s, int jc) {
        const int j0 = jc * KC;
#pragma unroll
        for (int k = 0; k < 4; ++k) {
            const int idx = tid + k * 256;
            const int r = idx >> 3;
            const int q = idx & 7;
            cp16(smb + A_OFF(s) + r * ROWB + q * 16, adjBase + (size_t)r * L + j0 + q * 4);
        }
#pragma unroll
        for (int k = 0; k < 2; ++k) {
            const int idx = tid + k * 256;
            const int r = idx >> 3;
            const int q = idx & 7;
            cp16(smb + B_OFF(s) + r * ROWB + q * 16, hT + (size_t)r * L + j0 + q * 4);
        }
        cp_commit();
    };

    // ldmatrix lane address offsets (bytes, within tile)
    const uint32_t aOff = (uint32_t)(wm * 32 + (lane & 15)) * ROWB + ((lane >> 4) << 4);
    const uint32_t bOff = (uint32_t)(wn * 32 + (lane & 7) + ((lane >> 4) << 3)) * ROWB
                          + (((lane >> 3) & 1) << 4);

    auto compute = [&](int s) {
        const uint32_t aS = smb + A_OFF(s) + aOff;
        const uint32_t bS = smb + B_OFF(s) + bOff;
#pragma unroll
        for (int ks = 0; ks < 4; ++ks) {
            uint32_t a[2][4];
            ldsm4(a[0], aS + ks * 32);
            ldsm4(a[1], aS + ks * 32 + 16 * ROWB);
#pragma unroll
            for (int p = 0; p < 2; ++p) {
                uint32_t bb[4];
                ldsm4(bb, bS + p * (16 * ROWB) + ks * 32);
#pragma unroll
                for (int mg = 0; mg < 2; ++mg) {
                    mma_tf32(c[mg][2 * p],     a[mg], bb[0], bb[1]);
                    mma_tf32(c[mg][2 * p + 1], a[mg], bb[2], bb[3]);
                }
            }
        }
    };

    prefetch(0, 0);
    prefetch(1, 1);
    prefetch(2, 2);

    for (int jc = 0; jc < NC; ++jc) {
        const int s = jc % NSTAGE;
        if (jc <= NC - 3)      cp_wait<2>();
        else if (jc == NC - 2) cp_wait<1>();
        else                   cp_wait<0>();
        __syncthreads();
        if (jc + 3 < NC) prefetch((jc + 3) % NSTAGE, jc + 3);
        compute(s);
    }

    // epilogue
    const float* sb = (const float*)(sm + BIAS_OFF);
#pragma unroll
    for (int mg = 0; mg < 2; ++mg) {
        const int r0 = i0 + wm * 32 + mg * 16 + gr;
#pragma unroll
        for (int n = 0; n < 4; ++n) {
            const int col = wn * 32 + n * 8 + 2 * cq;
            const float bx = sb[col], by = sb[col + 1];
            float* p0 = out + ((size_t)b * L + r0) * F + col;
            float* p1 = out + ((size_t)b * L + r0 + 8) * F + col;
            *(float2*)p0 = make_float2(c[mg][n][0] + bx, c[mg][n][1] + by);
            *(float2*)p1 = make_float2(c[mg][n][2] + bx, c[mg][n][3] + by);
        }
    }
}

extern "C" void kernel_launch(void* const* d_in, const int* in_sizes, int n_in,
                              void* d_out, int out_size)
{
    const float* text = (const float*)d_in[0];
    const float* adj  = (const float*)d_in[1];
    const float* W    = (const float*)d_in[2];
    const float* bias = (const float*)d_in[3];
    float* out = (float*)d_out;

    cudaFuncSetAttribute(gemm_mma_kernel,
                         cudaFuncAttributeMaxDynamicSharedMemorySize, SMEM_BYTES);

    hiddenT_kernel<<<dim3(L / 64, B), 512>>>(text, W);
    gemm_mma_kernel<<<dim3(L / TM, B), 256, SMEM_BYTES>>>(adj, bias, out);
}